// round 4
// baseline (speedup 1.0000x reference)
#include <cuda_runtime.h>

// GroundingDinoHungarianMatcher — fused focal-class-cost GEMM + bbox L1 + GIoU
// B=16, Q=900, C=512, T=40, L=91  ->  out [14400, 640] fp32
//
// NOTE: harness generates PTX for .target sm_103 (no 'a') — tcgen05/TMEM
// instructions are rejected by ptxas. Baseline-PTX FFMA GEMM only.
//
// Stage 1: W[640,512]  = normalized gathered label maps
// Stage 2: P[14400,512] = ALPHA*(1-p)^2*(-log(p+eps)) - (1-ALPHA)*p^2*(-log(1-p+eps))
// Stage 3: out = 2 * (P @ W^T) + 5 * L1(boxes) - 2 * GIoU(boxes)   (fused epilogue)
//
// GEMM: 128x128 block tile, 256 threads, 8x8 thread tile, BK=16,
//       double-buffered smem with ONE bar.sync per K-iteration.

#define BQ_TOT 14400
#define BT_TOT 640
#define CDIM   512
#define TDIM   40
#define LDIM   91

#define BM 128
#define BN 128
#define BK 16
#define NT (CDIM / BK)   // 32 K-iterations

// Scratch (allocation-free rule: __device__ globals)
__device__ float g_P[BQ_TOT * CDIM];   // ~29.5 MB
__device__ float g_W[BT_TOT * CDIM];   // ~1.3 MB

// ---------------------------------------------------------------------------
// Stage 1: gather label_maps rows by class label, normalize to sum 1
// ---------------------------------------------------------------------------
__global__ void compute_W_kernel(const float* __restrict__ label_maps,
                                 const int* __restrict__ class_labels) {
    int row = blockIdx.x;                 // 0..639 == b*T + t
    int b   = row / TDIM;
    int lbl = class_labels[row];
    const float* src = label_maps + ((size_t)b * LDIM + lbl) * CDIM;

    int tid = threadIdx.x;                // 256 threads, 2 elems each
    float v0 = src[tid];
    float v1 = src[tid + 256];

    __shared__ float red[256];
    red[tid] = v0 + v1;
    __syncthreads();
#pragma unroll
    for (int s = 128; s > 0; s >>= 1) {
        if (tid < s) red[tid] += red[tid + s];
        __syncthreads();
    }
    float inv = __fdividef(1.0f, red[0]);
    g_W[(size_t)row * CDIM + tid]       = v0 * inv;
    g_W[(size_t)row * CDIM + tid + 256] = v1 * inv;
}

// ---------------------------------------------------------------------------
// Stage 2: focal cost per logit element (vectorized float4)
// ---------------------------------------------------------------------------
__device__ __forceinline__ float focal_term(float x) {
    float p   = __fdividef(1.0f, 1.0f + __expf(-x));
    float omp = 1.0f - p;
    float pos = 0.25f * omp * omp * (-__logf(p + 1e-8f));
    float neg = 0.75f * p * p     * (-__logf(omp + 1e-8f));
    return pos - neg;
}

__global__ void compute_P_kernel(const float4* __restrict__ logits, int n4) {
    int i = blockIdx.x * blockDim.x + threadIdx.x;
    if (i >= n4) return;
    float4 x = logits[i];
    float4 r;
    r.x = focal_term(x.x);
    r.y = focal_term(x.y);
    r.z = focal_term(x.z);
    r.w = focal_term(x.w);
    reinterpret_cast<float4*>(g_P)[i] = r;
}

// ---------------------------------------------------------------------------
// Stage 3: tiled FP32 GEMM (P @ W^T) with fused bbox/GIoU epilogue
// ---------------------------------------------------------------------------
__global__ __launch_bounds__(256)
void gemm_epilogue_kernel(const float* __restrict__ pred_boxes,
                          const float* __restrict__ boxes,
                          float* __restrict__ out) {
    __shared__ float As[2][BK][BM + 4];  // K-major: As[buf][k][m]
    __shared__ float Bs[2][BK][BN + 4];  // Bs[buf][k][n]
    __shared__ float praw[BM][4];
    __shared__ float traw[BN][4];

    const int bm  = blockIdx.x * BM;
    const int bn  = blockIdx.y * BN;
    const int tid = threadIdx.x;
    const int tx  = tid & 15;            // N: 16 * 8 = 128
    const int ty  = tid >> 4;            // M: 16 * 8 = 128

    const int lrow  = tid >> 2;          // 0..63 (+64 second pass)
    const int lcol4 = tid & 3;           // float4 index along K

    float acc[8][8];
#pragma unroll
    for (int i = 0; i < 8; i++)
#pragma unroll
        for (int j = 0; j < 8; j++) acc[i][j] = 0.0f;

    float4 avA[2], avB[2];

    // ---- global load of K-tile `kt` into registers ----
    auto load_tile = [&](int kt) {
        int k0 = kt * BK;
#pragma unroll
        for (int r = 0; r < 2; ++r) {
            int arow = bm + lrow + r * 64;
            avA[r] = make_float4(0.f, 0.f, 0.f, 0.f);
            if (arow < BQ_TOT)
                avA[r] = *reinterpret_cast<const float4*>(
                    &g_P[(size_t)arow * CDIM + k0 + lcol4 * 4]);
            int brow = bn + lrow + r * 64;   // always < 640
            avB[r] = *reinterpret_cast<const float4*>(
                &g_W[(size_t)brow * CDIM + k0 + lcol4 * 4]);
        }
    };

    // ---- transpose-store registers into smem buffer `buf` ----
    auto store_tile = [&](int buf) {
#pragma unroll
        for (int r = 0; r < 2; ++r) {
            int m = lrow + r * 64;
            As[buf][lcol4 * 4 + 0][m] = avA[r].x;
            As[buf][lcol4 * 4 + 1][m] = avA[r].y;
            As[buf][lcol4 * 4 + 2][m] = avA[r].z;
            As[buf][lcol4 * 4 + 3][m] = avA[r].w;
            Bs[buf][lcol4 * 4 + 0][m] = avB[r].x;
            Bs[buf][lcol4 * 4 + 1][m] = avB[r].y;
            Bs[buf][lcol4 * 4 + 2][m] = avB[r].z;
            Bs[buf][lcol4 * 4 + 3][m] = avB[r].w;
        }
    };

    // ---- prologue: tile 0 -> smem[0]; tile 1 -> regs ----
    load_tile(0);
    store_tile(0);
    if (NT > 1) load_tile(1);
    __syncthreads();

    int cur = 0;
    for (int kt = 0; kt < NT; ++kt) {
        int nxt = cur ^ 1;
        // write tile kt+1 (in regs) to the other buffer: its last readers
        // finished at iter kt-1, separated by that iteration's bar.sync.
        if (kt + 1 < NT) store_tile(nxt);
        // issue global loads for tile kt+2 (consumed at iter kt+1's store)
        if (kt + 2 < NT) load_tile(kt + 2);

        // compute on smem[cur]
#pragma unroll
        for (int k = 0; k < BK; ++k) {
            float a[8], b[8];
            *reinterpret_cast<float4*>(&a[0]) = *reinterpret_cast<float4*>(&As[cur][k][ty * 8]);
            *reinterpret_cast<float4*>(&a[4]) = *reinterpret_cast<float4*>(&As[cur][k][ty * 8 + 4]);
            *reinterpret_cast<float4*>(&b[0]) = *reinterpret_cast<float4*>(&Bs[cur][k][tx * 8]);
            *reinterpret_cast<float4*>(&b[4]) = *reinterpret_cast<float4*>(&Bs[cur][k][tx * 8 + 4]);
#pragma unroll
            for (int i = 0; i < 8; i++)
#pragma unroll
                for (int j = 0; j < 8; j++)
                    acc[i][j] = fmaf(a[i], b[j], acc[i][j]);
        }
        __syncthreads();
        cur = nxt;
    }

    // ---- epilogue: stage raw boxes into smem ----
    if (tid < BN) {
        *reinterpret_cast<float4*>(&traw[tid][0]) =
            *reinterpret_cast<const float4*>(&boxes[(size_t)(bn + tid) * 4]);
    }
    if (tid < BM) {
        int r = bm + tid;
        float4 v = (r < BQ_TOT)
                 ? *reinterpret_cast<const float4*>(&pred_boxes[(size_t)r * 4])
                 : make_float4(0.5f, 0.5f, 1.0f, 1.0f);   // dummy, never stored
        *reinterpret_cast<float4*>(&praw[tid][0]) = v;
    }
    __syncthreads();

    // per-thread column data (8 target boxes)
    float tcx[8], tcy[8], twd[8], tht[8], tx0[8], ty0[8], tx1[8], ty1[8], ta[8];
#pragma unroll
    for (int j = 0; j < 8; j++) {
        float4 t = *reinterpret_cast<float4*>(&traw[tx * 8 + j][0]);
        tcx[j] = t.x; tcy[j] = t.y; twd[j] = t.z; tht[j] = t.w;
        tx0[j] = t.x - 0.5f * t.z; ty0[j] = t.y - 0.5f * t.w;
        tx1[j] = t.x + 0.5f * t.z; ty1[j] = t.y + 0.5f * t.w;
        ta[j]  = t.z * t.w;
    }

#pragma unroll
    for (int i = 0; i < 8; i++) {
        int grow = bm + ty * 8 + i;
        float4 p = *reinterpret_cast<float4*>(&praw[ty * 8 + i][0]);
        float pcx = p.x, pcy = p.y, pw = p.z, ph = p.w;
        float px0 = pcx - 0.5f * pw, py0 = pcy - 0.5f * ph;
        float px1 = pcx + 0.5f * pw, py1 = pcy + 0.5f * ph;
        float pa  = pw * ph;

        float res[8];
#pragma unroll
        for (int j = 0; j < 8; j++) {
            float cls  = 2.0f * acc[i][j];
            float bbox = fabsf(pcx - tcx[j]) + fabsf(pcy - tcy[j]) +
                         fabsf(pw  - twd[j]) + fabsf(ph  - tht[j]);
            // intersection
            float ltx = fmaxf(px0, tx0[j]), lty = fmaxf(py0, ty0[j]);
            float rbx = fminf(px1, tx1[j]), rby = fminf(py1, ty1[j]);
            float iw = fmaxf(rbx - ltx, 0.0f), ih = fmaxf(rby - lty, 0.0f);
            float inter = iw * ih;
            float uni   = pa + ta[j] - inter;
            float iou   = __fdividef(inter, uni);
            // enclosing box
            float ex0 = fminf(px0, tx0[j]), ey0 = fminf(py0, ty0[j]);
            float ex1 = fmaxf(px1, tx1[j]), ey1 = fmaxf(py1, ty1[j]);
            float ew = fmaxf(ex1 - ex0, 0.0f), eh = fmaxf(ey1 - ey0, 0.0f);
            float ae = ew * eh;
            float giou = iou - __fdividef(ae - uni, ae);
            res[j] = 5.0f * bbox + cls - 2.0f * giou;
        }
        if (grow < BQ_TOT) {
            *reinterpret_cast<float4*>(&out[(size_t)grow * BT_TOT + bn + tx * 8]) =
                *reinterpret_cast<float4*>(&res[0]);
            *reinterpret_cast<float4*>(&out[(size_t)grow * BT_TOT + bn + tx * 8 + 4]) =
                *reinterpret_cast<float4*>(&res[4]);
        }
    }
}

// ---------------------------------------------------------------------------
extern "C" void kernel_launch(void* const* d_in, const int* in_sizes, int n_in,
                              void* d_out, int out_size) {
    const float* logits       = (const float*)d_in[0];   // [16,900,512]
    const float* pred_boxes   = (const float*)d_in[1];   // [16,900,4]
    const float* label_maps   = (const float*)d_in[2];   // [16,91,512]
    const float* boxes        = (const float*)d_in[3];   // [16,40,4]
    const int*   class_labels = (const int*)  d_in[4];   // [16,40]
    float* out = (float*)d_out;                           // [16,900,640]

    compute_W_kernel<<<BT_TOT, 256>>>(label_maps, class_labels);

    const int n4 = BQ_TOT * CDIM / 4;                     // 1,843,200
    compute_P_kernel<<<(n4 + 255) / 256, 256>>>((const float4*)logits, n4);

    dim3 grid((BQ_TOT + BM - 1) / BM, BT_TOT / BN);       // 113 x 5
    gemm_epilogue_kernel<<<grid, 256>>>(pred_boxes, boxes, out);
}

// round 8
// speedup vs baseline: 4.1199x; 4.1199x over previous
#include <cuda_runtime.h>
#include <cuda_bf16.h>
#include <cstdint>

// GroundingDinoHungarianMatcher — bf16 mma.sync class-cost GEMM + fused L1/GIoU
// B=16, Q=900, C=512, T=40, L=91 -> out [14400, 640] fp32
//
// tcgen05 is blocked (harness PTX targets sm_103, not sm_103a), but
// mma.sync.m16n8k16 bf16 + ldmatrix are baseline PTX -> legacy HMMA path.
//
// Stage 1: W[640,512]  bf16 = normalized gathered label maps
// Stage 2: P[14400,512] bf16 = focal(logits)
// Stage 3: out = 2*(P@W^T) + 5*L1 - 2*GIoU
//   128x128 block, 8 warps (4Mx2N), warp tile 32x64, BK=32,
//   double-buffered swizzled smem, fp32 accumulators.

#define BQ_TOT 14400
#define BT_TOT 640
#define CDIM   512
#define TDIM   40
#define LDIM   91

#define BM 128
#define BN 128
#define BK 32
#define NT (CDIM / BK)   // 16

// Scratch (allocation-free rule)
__device__ __nv_bfloat16 g_Pb[(size_t)BQ_TOT * CDIM];   // 14.7 MB
__device__ __nv_bfloat16 g_Wb[(size_t)BT_TOT * CDIM];   // 0.66 MB

// ---------------- PTX helpers (baseline ISA only) ----------------
__device__ __forceinline__ uint32_t smem_u32(const void* p) {
    uint32_t a;
    asm("{ .reg .u64 t; cvta.to.shared.u64 t, %1; cvt.u32.u64 %0, t; }"
        : "=r"(a) : "l"(p));
    return a;
}
__device__ __forceinline__ void sts128(uint32_t addr, uint4 v) {
    asm volatile("st.shared.v4.b32 [%0], {%1,%2,%3,%4};"
                 :: "r"(addr), "r"(v.x), "r"(v.y), "r"(v.z), "r"(v.w) : "memory");
}
__device__ __forceinline__ void ldsm4(uint32_t* r, uint32_t addr) {
    asm volatile("ldmatrix.sync.aligned.m8n8.x4.shared.b16 {%0,%1,%2,%3}, [%4];"
                 : "=r"(r[0]), "=r"(r[1]), "=r"(r[2]), "=r"(r[3]) : "r"(addr));
}
__device__ __forceinline__ void mma16816(float* d, const uint32_t* a, const uint32_t* b) {
    asm volatile("mma.sync.aligned.m16n8k16.row.col.f32.bf16.bf16.f32 "
                 "{%0,%1,%2,%3},{%4,%5,%6,%7},{%8,%9},{%0,%1,%2,%3};"
                 : "+f"(d[0]), "+f"(d[1]), "+f"(d[2]), "+f"(d[3])
                 : "r"(a[0]), "r"(a[1]), "r"(a[2]), "r"(a[3]),
                   "r"(b[0]), "r"(b[1]));
}

// ---------------- Stage 1: W ----------------
__global__ void compute_W_kernel(const float* __restrict__ label_maps,
                                 const int* __restrict__ class_labels) {
    int row = blockIdx.x;                 // 0..639 == b*T + t
    int b   = row / TDIM;
    int lbl = class_labels[row];
    const float* src = label_maps + ((size_t)b * LDIM + lbl) * CDIM;

    int tid = threadIdx.x;
    float v0 = src[tid];
    float v1 = src[tid + 256];

    __shared__ float red[256];
    red[tid] = v0 + v1;
    __syncthreads();
#pragma unroll
    for (int s = 128; s > 0; s >>= 1) {
        if (tid < s) red[tid] += red[tid + s];
        __syncthreads();
    }
    float inv = __fdividef(1.0f, red[0]);
    g_Wb[(size_t)row * CDIM + tid]       = __float2bfloat16_rn(v0 * inv);
    g_Wb[(size_t)row * CDIM + tid + 256] = __float2bfloat16_rn(v1 * inv);
}

// ---------------- Stage 2: P (bf16 out) ----------------
__device__ __forceinline__ float focal_term(float x) {
    float p   = __fdividef(1.0f, 1.0f + __expf(-x));
    float omp = 1.0f - p;
    float pos = 0.25f * omp * omp * (-__logf(p + 1e-8f));
    float neg = 0.75f * p * p     * (-__logf(omp + 1e-8f));
    return pos - neg;
}

__global__ void compute_P_kernel(const float4* __restrict__ logits) {
    int i = blockIdx.x * blockDim.x + threadIdx.x;   // 8 elems per thread
    float4 a = logits[2 * i];
    float4 b = logits[2 * i + 1];
    __nv_bfloat162 p0 = __float22bfloat162_rn(make_float2(focal_term(a.x), focal_term(a.y)));
    __nv_bfloat162 p1 = __float22bfloat162_rn(make_float2(focal_term(a.z), focal_term(a.w)));
    __nv_bfloat162 p2 = __float22bfloat162_rn(make_float2(focal_term(b.x), focal_term(b.y)));
    __nv_bfloat162 p3 = __float22bfloat162_rn(make_float2(focal_term(b.z), focal_term(b.w)));
    uint4 o;
    o.x = *reinterpret_cast<uint32_t*>(&p0);
    o.y = *reinterpret_cast<uint32_t*>(&p1);
    o.z = *reinterpret_cast<uint32_t*>(&p2);
    o.w = *reinterpret_cast<uint32_t*>(&p3);
    reinterpret_cast<uint4*>(g_Pb)[i] = o;
}

// ---------------- Stage 3: mma.sync GEMM + fused epilogue ----------------
// smem tile layout: 128 rows x 64B (32 bf16); 16B chunk c of row r stored at
// byte r*64 + (c ^ ((r>>1)&3))*16  -> conflict-free for ldmatrix and STS.128.
__global__ __launch_bounds__(256)
void gemm_mma_kernel(const float* __restrict__ pred_boxes,
                     const float* __restrict__ boxes,
                     float* __restrict__ out) {
    __shared__ unsigned char sA[2][BM * BK * 2];    // 2 x 8KB
    __shared__ unsigned char sB[2][BN * BK * 2];    // 2 x 8KB
    __shared__ float4 praw[BM];
    __shared__ float4 traw[BN];

    const int tid  = threadIdx.x;
    const int lane = tid & 31;
    const int wid  = tid >> 5;
    const int wm   = wid & 3;        // 4 warps along M
    const int wn   = wid >> 2;       // 2 warps along N
    const int bm   = blockIdx.x * BM;
    const int bn   = blockIdx.y * BN;

    // ---- fill-index precompute (2 chunks of 16B per operand per thread) ----
    const int c0 = tid, c1 = tid + 256;
    const int r0 = c0 >> 2, kc0 = c0 & 3;
    const int r1 = c1 >> 2, kc1 = c1 & 3;
    const uint32_t so0 = (uint32_t)r0 * 64u + (uint32_t)((kc0 ^ ((r0 >> 1) & 3)) * 16);
    const uint32_t so1 = (uint32_t)r1 * 64u + (uint32_t)((kc1 ^ ((r1 >> 1) & 3)) * 16);

    uint32_t aAddr[2] = { smem_u32(sA[0]), smem_u32(sA[1]) };
    uint32_t bAddr[2] = { smem_u32(sB[0]), smem_u32(sB[1]) };

    uint4 vA0, vA1, vB0, vB1;
    auto load_tile = [&](int kt) {
        size_t gk = (size_t)kt * BK;
        int ga0 = bm + r0, ga1 = bm + r1;
        vA0 = (ga0 < BQ_TOT)
            ? *reinterpret_cast<const uint4*>(g_Pb + (size_t)ga0 * CDIM + gk + kc0 * 8)
            : make_uint4(0u, 0u, 0u, 0u);
        vA1 = (ga1 < BQ_TOT)
            ? *reinterpret_cast<const uint4*>(g_Pb + (size_t)ga1 * CDIM + gk + kc1 * 8)
            : make_uint4(0u, 0u, 0u, 0u);
        vB0 = *reinterpret_cast<const uint4*>(g_Wb + (size_t)(bn + r0) * CDIM + gk + kc0 * 8);
        vB1 = *reinterpret_cast<const uint4*>(g_Wb + (size_t)(bn + r1) * CDIM + gk + kc1 * 8);
    };
    auto store_tile = [&](int buf) {
        sts128(aAddr[buf] + so0, vA0);
        sts128(aAddr[buf] + so1, vA1);
        sts128(bAddr[buf] + so0, vB0);
        sts128(bAddr[buf] + so1, vB1);
    };

    // ---- ldmatrix lane geometry ----
    // A x4 groups: g0=(m0-7,klo) g1=(m8-15,klo) g2=(m0-7,khi) g3=(m8-15,khi)
    // B x4 groups: g0=(n0-7,klo) g1=(n0-7,khi) g2=(n8-15,klo) g3=(n8-15,khi)
    const int g  = lane >> 3;
    const int lr = lane & 7;
    const int acg = g >> 1;          // A k-chunk subsel
    const int bcg = g & 1;           // B k-chunk subsel

    uint32_t aoff[2]; int amask[2];
    {
        int row0 = wm * 32 + (g & 1) * 8 + lr;
        aoff[0] = (uint32_t)row0 * 64u;        amask[0] = (row0 >> 1) & 3;
        int row1 = row0 + 16;
        aoff[1] = (uint32_t)row1 * 64u;        amask[1] = (row1 >> 1) & 3;
    }
    uint32_t boff[4]; int bmask[4];
#pragma unroll
    for (int nt = 0; nt < 4; nt++) {
        int row = wn * 64 + nt * 16 + (g >> 1) * 8 + lr;
        boff[nt] = (uint32_t)row * 64u;        bmask[nt] = (row >> 1) & 3;
    }

    float acc[2][8][4];
#pragma unroll
    for (int i = 0; i < 2; i++)
#pragma unroll
        for (int j = 0; j < 8; j++)
#pragma unroll
            for (int k = 0; k < 4; k++) acc[i][j][k] = 0.0f;

    // ---- prologue ----
    load_tile(0);
    store_tile(0);
    load_tile(1);
    __syncthreads();

    int cur = 0;
    for (int kt = 0; kt < NT; ++kt) {
        int nxt = cur ^ 1;
        if (kt + 1 < NT) store_tile(nxt);     // safe: last readers of nxt synced at kt-1
        if (kt + 2 < NT) load_tile(kt + 2);

        uint32_t aB = aAddr[cur], bB = bAddr[cur];
#pragma unroll
        for (int s = 0; s < 2; ++s) {         // two k16 steps per BK=32
            uint32_t af[2][4], bf[4][4];
#pragma unroll
            for (int mt = 0; mt < 2; mt++) {
                uint32_t ch = (uint32_t)(((acg + 2 * s) ^ amask[mt]) * 16);
                ldsm4(af[mt], aB + aoff[mt] + ch);
            }
#pragma unroll
            for (int nt = 0; nt < 4; nt++) {
                uint32_t ch = (uint32_t)(((bcg + 2 * s) ^ bmask[nt]) * 16);
                ldsm4(bf[nt], bB + boff[nt] + ch);
            }
#pragma unroll
            for (int mt = 0; mt < 2; mt++)
#pragma unroll
                for (int n8 = 0; n8 < 8; n8++)
                    mma16816(acc[mt][n8], af[mt], &bf[n8 >> 1][(n8 & 1) * 2]);
        }
        __syncthreads();
        cur = nxt;
    }

    // ---- epilogue: stage boxes ----
    if (tid < BN)
        traw[tid] = *reinterpret_cast<const float4*>(boxes + (size_t)(bn + tid) * 4);
    if (tid < BM) {
        int r = bm + tid;
        praw[tid] = (r < BQ_TOT)
                  ? *reinterpret_cast<const float4*>(pred_boxes + (size_t)r * 4)
                  : make_float4(0.5f, 0.5f, 1.0f, 1.0f);
    }
    __syncthreads();

    const int qr = lane >> 2;
    const int qc = (lane & 3) * 2;

#pragma unroll
    for (int mt = 0; mt < 2; mt++)
#pragma unroll
    for (int hf = 0; hf < 2; hf++) {
        int mrow = wm * 32 + mt * 16 + hf * 8 + qr;
        int grow = bm + mrow;
        if (grow >= BQ_TOT) continue;
        float4 p = praw[mrow];
        float pcx = p.x, pcy = p.y, pw = p.z, ph = p.w;
        float px0 = pcx - 0.5f * pw, py0 = pcy - 0.5f * ph;
        float px1 = pcx + 0.5f * pw, py1 = pcy + 0.5f * ph;
        float pa  = pw * ph;
        float* orow = out + (size_t)grow * BT_TOT + bn;

#pragma unroll
        for (int n8 = 0; n8 < 8; n8++) {
            int ccol = wn * 64 + n8 * 8 + qc;
            float2 res;
            float* rp = &res.x;
#pragma unroll
            for (int jj = 0; jj < 2; jj++) {
                float4 t = traw[ccol + jj];
                float cls = 2.0f * acc[mt][n8][hf * 2 + jj];
                float bb  = fabsf(pcx - t.x) + fabsf(pcy - t.y) +
                            fabsf(pw  - t.z) + fabsf(ph  - t.w);
                float tx0 = t.x - 0.5f * t.z, ty0 = t.y - 0.5f * t.w;
                float tx1 = t.x + 0.5f * t.z, ty1 = t.y + 0.5f * t.w;
                float ta  = t.z * t.w;
                float iw  = fmaxf(fminf(px1, tx1) - fmaxf(px0, tx0), 0.0f);
                float ih  = fmaxf(fminf(py1, ty1) - fmaxf(py0, ty0), 0.0f);
                float inter = iw * ih;
                float uni   = pa + ta - inter;
                float ew = fmaxf(px1, tx1) - fminf(px0, tx0);
                float eh = fmaxf(py1, ty1) - fminf(py0, ty0);
                float ae = ew * eh;
                float giou = __fdividef(inter, uni) - __fdividef(ae - uni, ae);
                rp[jj] = 5.0f * bb + cls - 2.0f * giou;
            }
            *reinterpret_cast<float2*>(orow + ccol) = res;
        }
    }
}

// ---------------- launch ----------------
extern "C" void kernel_launch(void* const* d_in, const int* in_sizes, int n_in,
                              void* d_out, int out_size) {
    const float* logits       = (const float*)d_in[0];   // [16,900,512]
    const float* pred_boxes   = (const float*)d_in[1];   // [16,900,4]
    const float* label_maps   = (const float*)d_in[2];   // [16,91,512]
    const float* boxes        = (const float*)d_in[3];   // [16,40,4]
    const int*   class_labels = (const int*)  d_in[4];   // [16,40]
    float* out = (float*)d_out;                           // [16,900,640]

    compute_W_kernel<<<BT_TOT, 256>>>(label_maps, class_labels);

    const int n8 = BQ_TOT * CDIM / 8;                     // 921600
    compute_P_kernel<<<n8 / 256, 256>>>((const float4*)logits);

    dim3 grid((BQ_TOT + BM - 1) / BM, BT_TOT / BN);       // 113 x 5
    gemm_mma_kernel<<<grid, 256>>>(pred_boxes, boxes, out);
}

// round 13
// speedup vs baseline: 4.7452x; 1.1518x over previous
#include <cuda_runtime.h>
#include <cuda_bf16.h>
#include <cstdint>

// GroundingDinoHungarianMatcher — bf16 mma.sync GEMM + fused L1/GIoU
// R13 == R10..R12: cp.async 4-stage pipeline, W fused into P launch, 2 CTAs/SM.
// Resubmitted unchanged (broker timeouts; never executed).

#define BQ_TOT 14400
#define BT_TOT 640
#define CDIM   512
#define TDIM   40
#define LDIM   91

#define BM 128
#define BN 128
#define BK 32
#define NT (CDIM / BK)     // 16
#define STAGES 4
#define NP_BLOCKS 3600     // P-part blocks in fused WP kernel

// Scratch (allocation-free rule)
__device__ __nv_bfloat16 g_Pb[(size_t)BQ_TOT * CDIM];   // 14.7 MB
__device__ __nv_bfloat16 g_Wb[(size_t)BT_TOT * CDIM];   // 0.66 MB

// ---------------- PTX helpers (baseline ISA only) ----------------
__device__ __forceinline__ uint32_t smem_u32(const void* p) {
    uint32_t a;
    asm("{ .reg .u64 t; cvta.to.shared.u64 t, %1; cvt.u32.u64 %0, t; }"
        : "=r"(a) : "l"(p));
    return a;
}
__device__ __forceinline__ void cp16(uint32_t dst, const void* src, uint32_t nbytes) {
    // cp-size 16; src_size nbytes (0 -> whole dst 16B zero-filled)
    asm volatile("cp.async.cg.shared.global [%0], [%1], 16, %2;"
                 :: "r"(dst), "l"(src), "r"(nbytes) : "memory");
}
__device__ __forceinline__ void cp_commit() {
    asm volatile("cp.async.commit_group;" ::: "memory");
}
__device__ __forceinline__ void cp_wait2() {
    asm volatile("cp.async.wait_group 2;" ::: "memory");
}
__device__ __forceinline__ void ldsm4(uint32_t* r, uint32_t addr) {
    asm volatile("ldmatrix.sync.aligned.m8n8.x4.shared.b16 {%0,%1,%2,%3}, [%4];"
                 : "=r"(r[0]), "=r"(r[1]), "=r"(r[2]), "=r"(r[3]) : "r"(addr));
}
__device__ __forceinline__ void mma16816(float* d, const uint32_t* a, const uint32_t* b) {
    asm volatile("mma.sync.aligned.m16n8k16.row.col.f32.bf16.bf16.f32 "
                 "{%0,%1,%2,%3},{%4,%5,%6,%7},{%8,%9},{%0,%1,%2,%3};"
                 : "+f"(d[0]), "+f"(d[1]), "+f"(d[2]), "+f"(d[3])
                 : "r"(a[0]), "r"(a[1]), "r"(a[2]), "r"(a[3]),
                   "r"(b[0]), "r"(b[1]));
}

// ---------------- fused Stage 1+2: W and P in one launch ----------------
__device__ __forceinline__ float focal_term(float x) {
    float p   = __fdividef(1.0f, 1.0f + __expf(-x));
    float omp = 1.0f - p;
    float pos = 0.25f * omp * omp * (-__logf(p + 1e-8f));
    float neg = 0.75f * p * p     * (-__logf(omp + 1e-8f));
    return pos - neg;
}

__global__ void fused_WP_kernel(const float4* __restrict__ logits,
                                const float* __restrict__ label_maps,
                                const int* __restrict__ class_labels) {
    __shared__ float red[256];
    int tid = threadIdx.x;

    if (blockIdx.x < NP_BLOCKS) {
        // ---- P part: 8 focal terms per thread ----
        int i = blockIdx.x * 256 + tid;
        float4 a = logits[2 * i];
        float4 b = logits[2 * i + 1];
        __nv_bfloat162 p0 = __float22bfloat162_rn(make_float2(focal_term(a.x), focal_term(a.y)));
        __nv_bfloat162 p1 = __float22bfloat162_rn(make_float2(focal_term(a.z), focal_term(a.w)));
        __nv_bfloat162 p2 = __float22bfloat162_rn(make_float2(focal_term(b.x), focal_term(b.y)));
        __nv_bfloat162 p3 = __float22bfloat162_rn(make_float2(focal_term(b.z), focal_term(b.w)));
        uint4 o;
        o.x = *reinterpret_cast<uint32_t*>(&p0);
        o.y = *reinterpret_cast<uint32_t*>(&p1);
        o.z = *reinterpret_cast<uint32_t*>(&p2);
        o.w = *reinterpret_cast<uint32_t*>(&p3);
        reinterpret_cast<uint4*>(g_Pb)[i] = o;
    } else {
        // ---- W part: gather + normalize one row ----
        int row = blockIdx.x - NP_BLOCKS;        // 0..639
        int b   = row / TDIM;
        int lbl = class_labels[row];
        const float* src = label_maps + ((size_t)b * LDIM + lbl) * CDIM;

        float v0 = src[tid];
        float v1 = src[tid + 256];
        red[tid] = v0 + v1;
        __syncthreads();
#pragma unroll
        for (int s = 128; s > 0; s >>= 1) {
            if (tid < s) red[tid] += red[tid + s];
            __syncthreads();
        }
        float inv = __fdividef(1.0f, red[0]);
        g_Wb[(size_t)row * CDIM + tid]       = __float2bfloat16_rn(v0 * inv);
        g_Wb[(size_t)row * CDIM + tid + 256] = __float2bfloat16_rn(v1 * inv);
    }
}

// ---------------- Stage 3: cp.async-pipelined mma.sync GEMM ----------------
// Dynamic smem layout (bytes from base):
//   sA stage s : s*8192              (4 x 8KB)
//   sB stage s : 32768 + s*8192      (4 x 8KB)
//   praw       : 65536  (128 x float4 = 2KB)
//   traw       : 67584  (128 x float4 = 2KB)
#define SMEM_BYTES (69632)
// smem tile: 128 rows x 64B; 16B chunk c of row r at r*64 + ((c ^ ((r>>1)&3))*16)

__global__ __launch_bounds__(256, 2)
void gemm_mma_kernel(const float* __restrict__ pred_boxes,
                     const float* __restrict__ boxes,
                     float* __restrict__ out) {
    extern __shared__ unsigned char smem[];
    const uint32_t sbase = smem_u32(smem);
    float4* praw = reinterpret_cast<float4*>(smem + 65536);
    float4* traw = reinterpret_cast<float4*>(smem + 67584);

    const int tid  = threadIdx.x;
    const int lane = tid & 31;
    const int wid  = tid >> 5;
    const int wm   = wid & 3;        // 4 warps along M
    const int wn   = wid >> 2;       // 2 warps along N
    const int bm   = blockIdx.x * BM;
    const int bn   = blockIdx.y * BN;

    // ---- fill-index precompute (2 x 16B per operand per thread) ----
    const int c0 = tid, c1 = tid + 256;
    const int r0 = c0 >> 2, kc0 = c0 & 3;
    const int r1 = c1 >> 2, kc1 = c1 & 3;
    const uint32_t so0 = (uint32_t)r0 * 64u + (uint32_t)((kc0 ^ ((r0 >> 1) & 3)) * 16);
    const uint32_t so1 = (uint32_t)r1 * 64u + (uint32_t)((kc1 ^ ((r1 >> 1) & 3)) * 16);

    const uint32_t na0 = (bm + r0 < BQ_TOT) ? 16u : 0u;   // zero-fill OOB A rows
    const uint32_t na1 = (bm + r1 < BQ_TOT) ? 16u : 0u;
    const int ga0 = (bm + r0 < BQ_TOT) ? (bm + r0) : (BQ_TOT - 1);
    const int ga1 = (bm + r1 < BQ_TOT) ? (bm + r1) : (BQ_TOT - 1);

    auto fill_stage = [&](int st, int kt) {
        size_t gk = (size_t)kt * BK;
        uint32_t aS = sbase + (uint32_t)st * 8192u;
        uint32_t bS = sbase + 32768u + (uint32_t)st * 8192u;
        cp16(aS + so0, g_Pb + (size_t)ga0 * CDIM + gk + kc0 * 8, na0);
        cp16(aS + so1, g_Pb + (size_t)ga1 * CDIM + gk + kc1 * 8, na1);
        cp16(bS + so0, g_Wb + (size_t)(bn + r0) * CDIM + gk + kc0 * 8, 16u);
        cp16(bS + so1, g_Wb + (size_t)(bn + r1) * CDIM + gk + kc1 * 8, 16u);
    };

    // ---- ldmatrix lane geometry ----
    const int g  = lane >> 3;
    const int lr = lane & 7;
    const int acg = g >> 1;          // A k-chunk subsel
    const int bcg = g & 1;           // B k-chunk subsel

    uint32_t aoff[2]; int amask[2];
    {
        int row0 = wm * 32 + (g & 1) * 8 + lr;
        aoff[0] = (uint32_t)row0 * 64u;        amask[0] = (row0 >> 1) & 3;
        int row1 = row0 + 16;
        aoff[1] = (uint32_t)row1 * 64u;        amask[1] = (row1 >> 1) & 3;
    }
    uint32_t boff[4]; int bmask[4];
#pragma unroll
    for (int nt = 0; nt < 4; nt++) {
        int row = wn * 64 + nt * 16 + (g >> 1) * 8 + lr;
        boff[nt] = (uint32_t)row * 64u;        bmask[nt] = (row >> 1) & 3;
    }

    float acc[2][8][4];
#pragma unroll
    for (int i = 0; i < 2; i++)
#pragma unroll
        for (int j = 0; j < 8; j++)
#pragma unroll
            for (int k = 0; k < 4; k++) acc[i][j][k] = 0.0f;

    // ---- prologue: stages 0..2 in flight ----
#pragma unroll
    for (int s = 0; s < STAGES - 1; ++s) { fill_stage(s, s); cp_commit(); }

    for (int kt = 0; kt < NT; ++kt) {
        cp_wait2();                 // stage kt data arrived (this thread)
        __syncthreads();            // all threads waited -> stage kt fully visible;
                                    // also orders iter kt-1 readers before refill
        if (kt + STAGES - 1 < NT) fill_stage((kt + STAGES - 1) & 3, kt + STAGES - 1);
        cp_commit();                // keep group count uniform (empty ok)

        uint32_t aB = sbase + (uint32_t)(kt & 3) * 8192u;
        uint32_t bB = sbase + 32768u + (uint32_t)(kt & 3) * 8192u;
#pragma unroll
        for (int s = 0; s < 2; ++s) {         // two k16 steps per BK=32
            uint32_t af[2][4], bf[4][4];
#pragma unroll
            for (int mt = 0; mt < 2; mt++) {
                uint32_t ch = (uint32_t)(((acg + 2 * s) ^ amask[mt]) * 16);
                ldsm4(af[mt], aB + aoff[mt] + ch);
            }
#pragma unroll
            for (int nt = 0; nt < 4; nt++) {
                uint32_t ch = (uint32_t)(((bcg + 2 * s) ^ bmask[nt]) * 16);
                ldsm4(bf[nt], bB + boff[nt] + ch);
            }
#pragma unroll
            for (int mt = 0; mt < 2; mt++)
#pragma unroll
                for (int n8 = 0; n8 < 8; n8++)
                    mma16816(acc[mt][n8], af[mt], &bf[n8 >> 1][(n8 & 1) * 2]);
        }
    }

    // ---- epilogue: stage boxes ----
    __syncthreads();
    if (tid < BN)
        traw[tid] = *reinterpret_cast<const float4*>(boxes + (size_t)(bn + tid) * 4);
    if (tid < BM) {
        int r = bm + tid;
        praw[tid] = (r < BQ_TOT)
                  ? *reinterpret_cast<const float4*>(pred_boxes + (size_t)r * 4)
                  : make_float4(0.5f, 0.5f, 1.0f, 1.0f);
    }
    __syncthreads();

    const int qr = lane >> 2;
    const int qc = (lane & 3) * 2;

#pragma unroll
    for (int mt = 0; mt < 2; mt++)
#pragma unroll
    for (int hf = 0; hf < 2; hf++) {
        int mrow = wm * 32 + mt * 16 + hf * 8 + qr;
        int grow = bm + mrow;
        if (grow >= BQ_TOT) continue;
        float4 p = praw[mrow];
        float pcx = p.x, pcy = p.y, pw = p.z, ph = p.w;
        float px0 = pcx - 0.5f * pw, py0 = pcy - 0.5f * ph;
        float px1 = pcx + 0.5f * pw, py1 = pcy + 0.5f * ph;
        float pa  = pw * ph;
        float* orow = out + (size_t)grow * BT_TOT + bn;

#pragma unroll
        for (int n8 = 0; n8 < 8; n8++) {
            int ccol = wn * 64 + n8 * 8 + qc;
            float2 res;
            float* rp = &res.x;
#pragma unroll
            for (int jj = 0; jj < 2; jj++) {
                float4 t = traw[ccol + jj];
                float cls = 2.0f * acc[mt][n8][hf * 2 + jj];
                float bb  = fabsf(pcx - t.x) + fabsf(pcy - t.y) +
                            fabsf(pw  - t.z) + fabsf(ph  - t.w);
                float tx0 = t.x - 0.5f * t.z, ty0 = t.y - 0.5f * t.w;
                float tx1 = t.x + 0.5f * t.z, ty1 = t.y + 0.5f * t.w;
                float ta  = t.z * t.w;
                float iw  = fmaxf(fminf(px1, tx1) - fmaxf(px0, tx0), 0.0f);
                float ih  = fmaxf(fminf(py1, ty1) - fmaxf(py0, ty0), 0.0f);
                float inter = iw * ih;
                float uni   = pa + ta - inter;
                float ew = fmaxf(px1, tx1) - fminf(px0, tx0);
                float eh = fmaxf(py1, ty1) - fminf(py0, ty0);
                float ae = ew * eh;
                float giou = __fdividef(inter, uni) - __fdividef(ae - uni, ae);
                rp[jj] = 5.0f * bb + cls - 2.0f * giou;
            }
            *reinterpret_cast<float2*>(orow + ccol) = res;
        }
    }
}

// ---------------- launch ----------------
extern "C" void kernel_launch(void* const* d_in, const int* in_sizes, int n_in,
                              void* d_out, int out_size) {
    const float* logits       = (const float*)d_in[0];   // [16,900,512]
    const float* pred_boxes   = (const float*)d_in[1];   // [16,900,4]
    const float* label_maps   = (const float*)d_in[2];   // [16,91,512]
    const float* boxes        = (const float*)d_in[3];   // [16,40,4]
    const int*   class_labels = (const int*)  d_in[4];   // [16,40]
    float* out = (float*)d_out;                           // [16,900,640]

    // Unconditional (idempotent, host-side, capture-safe) — no static guards.
    cudaFuncSetAttribute(gemm_mma_kernel,
                         cudaFuncAttributeMaxDynamicSharedMemorySize, SMEM_BYTES);

    fused_WP_kernel<<<NP_BLOCKS + BT_TOT, 256>>>((const float4*)logits,
                                                 label_maps, class_labels);

    dim3 grid((BQ_TOT + BM - 1) / BM, BT_TOT / BN);       // 113 x 5
    gemm_mma_kernel<<<grid, 256, SMEM_BYTES>>>(pred_boxes, boxes, out);
}